// round 1
// baseline (speedup 1.0000x reference)
#include <cuda_runtime.h>
#include <math.h>

#define NB   127          // num bonds (cores[:-1])
#define NDIM 256          // r_right
#define KDIM 1024         // r_left * d_k
#define PACK ((NDIM * (NDIM + 1)) / 2)   // 32896 packed lower-tri floats

// Device scratch (static allocation is allowed; cudaMalloc is not)
static __device__ float g_G[(size_t)NB * NDIM * NDIM];   // Gram matrices (lower triangle valid)
static __device__ float g_d[NB * NDIM];                   // tridiagonal diag
static __device__ float g_e[NB * NDIM];                   // tridiagonal off-diag (e[0]=0)
static __device__ float g_partial[NB];                    // per-bond nuclear norms

// ------------------------------------------------------------------
// Reduction helpers
// ------------------------------------------------------------------
__device__ __forceinline__ float warp_sum(float v) {
#pragma unroll
    for (int o = 16; o > 0; o >>= 1) v += __shfl_xor_sync(0xffffffffu, v, o);
    return v;
}
__device__ __forceinline__ float warp_min(float v) {
#pragma unroll
    for (int o = 16; o > 0; o >>= 1) v = fminf(v, __shfl_xor_sync(0xffffffffu, v, o));
    return v;
}
__device__ __forceinline__ float warp_max(float v) {
#pragma unroll
    for (int o = 16; o > 0; o >>= 1) v = fmaxf(v, __shfl_xor_sync(0xffffffffu, v, o));
    return v;
}

// Block reduce (blockDim.x threads, must be called by ALL threads). red: >= 32 floats.
__device__ float block_sum(float v, float* red) {
    int lane = threadIdx.x & 31, w = threadIdx.x >> 5;
    int nw = (blockDim.x + 31) >> 5;
    v = warp_sum(v);
    if (lane == 0) red[w] = v;
    __syncthreads();
    if (w == 0) {
        float t = (lane < nw) ? red[lane] : 0.f;
        t = warp_sum(t);
        if (lane == 0) red[0] = t;
    }
    __syncthreads();
    float r = red[0];
    __syncthreads();
    return r;
}
__device__ float block_min(float v, float* red) {
    int lane = threadIdx.x & 31, w = threadIdx.x >> 5;
    int nw = (blockDim.x + 31) >> 5;
    v = warp_min(v);
    if (lane == 0) red[w] = v;
    __syncthreads();
    if (w == 0) {
        float t = (lane < nw) ? red[lane] : 3.4e38f;
        t = warp_min(t);
        if (lane == 0) red[0] = t;
    }
    __syncthreads();
    float r = red[0];
    __syncthreads();
    return r;
}
__device__ float block_max(float v, float* red) {
    int lane = threadIdx.x & 31, w = threadIdx.x >> 5;
    int nw = (blockDim.x + 31) >> 5;
    v = warp_max(v);
    if (lane == 0) red[w] = v;
    __syncthreads();
    if (w == 0) {
        float t = (lane < nw) ? red[lane] : -3.4e38f;
        t = warp_max(t);
        if (lane == 0) red[0] = t;
    }
    __syncthreads();
    float r = red[0];
    __syncthreads();
    return r;
}

// ------------------------------------------------------------------
// Kernel 1: Gram. G_b = M_b^T M_b. Only lower-triangle 64x64 tiles.
// grid: (10 tile-pairs, 1, NB). block: (16, 16).
// ------------------------------------------------------------------
__global__ void gram_kernel(const float* __restrict__ A) {
    const int TI[10] = {0, 1, 1, 2, 2, 2, 3, 3, 3, 3};
    const int TJ[10] = {0, 0, 1, 0, 1, 2, 0, 1, 2, 3};

    __shared__ float As[16][64];
    __shared__ float Bs[16][64];

    int b = blockIdx.z;
    int ti = TI[blockIdx.x], tj = TJ[blockIdx.x];
    const float* M = A + (size_t)b * KDIM * NDIM;
    int i0 = ti * 64, j0 = tj * 64;
    int tx = threadIdx.x, ty = threadIdx.y;
    int tid = ty * 16 + tx;

    float c[4][4];
#pragma unroll
    for (int ii = 0; ii < 4; ii++)
#pragma unroll
        for (int jj = 0; jj < 4; jj++) c[ii][jj] = 0.f;

    for (int k0 = 0; k0 < KDIM; k0 += 16) {
#pragma unroll
        for (int r = 0; r < 4; r++) {
            int e = tid + r * 256;
            int kk = e >> 6, col = e & 63;
            size_t base = (size_t)(k0 + kk) * NDIM;
            As[kk][col] = M[base + i0 + col];
            Bs[kk][col] = M[base + j0 + col];
        }
        __syncthreads();
#pragma unroll
        for (int kk = 0; kk < 16; kk++) {
            float a[4], bb[4];
#pragma unroll
            for (int ii = 0; ii < 4; ii++) a[ii] = As[kk][ii * 16 + ty];
#pragma unroll
            for (int jj = 0; jj < 4; jj++) bb[jj] = Bs[kk][jj * 16 + tx];
#pragma unroll
            for (int ii = 0; ii < 4; ii++)
#pragma unroll
                for (int jj = 0; jj < 4; jj++) c[ii][jj] = fmaf(a[ii], bb[jj], c[ii][jj]);
        }
        __syncthreads();
    }

    float* G = g_G + (size_t)b * NDIM * NDIM;
#pragma unroll
    for (int ii = 0; ii < 4; ii++) {
        int gi = i0 + ii * 16 + ty;
#pragma unroll
        for (int jj = 0; jj < 4; jj++) {
            int gj = j0 + jj * 16 + tx;
            G[(size_t)gi * NDIM + gj] = c[ii][jj];
        }
    }
}

// ------------------------------------------------------------------
// Kernel 2: Householder tridiagonalization (eigenvalue-only tred2),
// packed lower triangle in dynamic shared memory. One CTA per bond.
// block: 256 threads.
// smem layout: ap[PACK] | p[N] | q[N] | earr[N] | red[32]
// ------------------------------------------------------------------
__global__ void tridiag_kernel() {
    extern __shared__ float sm[];
    float* ap   = sm;
    float* p    = sm + PACK;
    float* qq   = p + NDIM;
    float* earr = qq + NDIM;
    float* red  = earr + NDIM;

    int b = blockIdx.x;
    int tid = threadIdx.x;
    const float* G = g_G + (size_t)b * NDIM * NDIM;

    // load packed lower triangle
    for (int i = 0; i < NDIM; i++) {
        int ro = (i * (i + 1)) >> 1;
        for (int j = tid; j <= i; j += 256) ap[ro + j] = G[(size_t)i * NDIM + j];
    }
    if (tid == 0) earr[0] = 0.f;
    __syncthreads();

    for (int i = NDIM - 1; i >= 1; --i) {
        int m = i;                       // length of Householder vector
        float* u = ap + ((i * (i + 1)) >> 1);   // row i of packed lower (contiguous)

        if (m == 1) {
            if (tid == 0) earr[1] = u[0];
            __syncthreads();
            continue;
        }

        // sigma = sum u^2
        float part = 0.f;
        for (int l = tid; l < m; l += 256) part += u[l] * u[l];
        float sigma = block_sum(part, red);

        if (sigma <= 0.f) {              // uniform branch (sigma broadcast)
            if (tid == 0) earr[i] = 0.f;
            __syncthreads();
            continue;
        }

        float f = u[m - 1];
        float g = (f >= 0.f) ? -sqrtf(sigma) : sqrtf(sigma);
        float h = sigma - f * g;
        if (tid == 0) { earr[i] = g; u[m - 1] = f - g; }
        __syncthreads();

        // p = A u / h  over leading m x m block
        int j = tid;
        if (j < m) {
            int rj = (j * (j + 1)) >> 1;
            float pj = 0.f;
            int rol = 0;
            for (int l = 0; l < m; ++l) {
                float ul = u[l];                          // smem broadcast
                float av = (l <= j) ? ap[rj + l] : ap[rol + j];
                pj = fmaf(av, ul, pj);
                rol += l + 1;
            }
            p[j] = pj / h;
        }
        __syncthreads();

        // K = u.p / (2h);  q = p - K u
        float kp = (j < m) ? u[j] * p[j] : 0.f;
        float K = block_sum(kp, red) / (2.f * h);
        if (j < m) qq[j] = p[j] - K * u[j];
        __syncthreads();

        // rank-2 update: A -= u q^T + q u^T (lower triangle)
        if (j < m) {
            float uj = u[j], qj = qq[j];
            float* rowj = ap + ((j * (j + 1)) >> 1);
            for (int l = 0; l <= j; ++l)
                rowj[l] -= uj * qq[l] + qj * u[l];
        }
        __syncthreads();
    }

    // extract tridiagonal
    for (int ii = tid; ii < NDIM; ii += 256) {
        g_d[b * NDIM + ii] = ap[((ii * (ii + 1)) >> 1) + ii];
        g_e[b * NDIM + ii] = earr[ii];
    }
}

// ------------------------------------------------------------------
// Kernel 3: bisection eigenvalues via Sturm counts + sum of sqrt.
// One CTA per bond, 256 threads = 256 eigenvalues.
// ------------------------------------------------------------------
__global__ void eig_kernel() {
    __shared__ float dd[NDIM];
    __shared__ float e2[NDIM];
    __shared__ float red[32];

    int b = blockIdx.x;
    int k = threadIdx.x;

    float dk = g_d[b * NDIM + k];
    float ek = g_e[b * NDIM + k];
    dd[k] = dk;
    e2[k] = ek * ek;
    __syncthreads();

    // Gershgorin bounds
    float ein = (k + 1 < NDIM) ? fabsf(g_e[b * NDIM + k + 1]) : 0.f;
    float rad = fabsf(ek) + ein;
    float glo = block_min(dk - rad, red) - 1.f;
    float ghi = block_max(dk + rad, red) + 1.f;

    float a = glo, bnd = ghi;
#pragma unroll 1
    for (int it = 0; it < 42; ++it) {
        float x = 0.5f * (a + bnd);
        // Sturm count: number of eigenvalues < x
        int cnt = 0;
        float qv = dd[0] - x;
        cnt += (qv < 0.f);
#pragma unroll 8
        for (int ii = 1; ii < NDIM; ++ii) {
            qv = (dd[ii] - x) - __fdividef(e2[ii], qv);
            cnt += (qv < 0.f);
        }
        if (cnt >= k + 1) bnd = x;
        else              a = x;
    }
    float lam = 0.5f * (a + bnd);
    float s = sqrtf(fmaxf(lam, 0.f));

    float tot = block_sum(s, red);
    if (k == 0) g_partial[b] = tot;
}

// ------------------------------------------------------------------
// Kernel 4: final scalar
// ------------------------------------------------------------------
__global__ void final_kernel(float* __restrict__ out) {
    __shared__ float red[32];
    float v = 0.f;
    for (int i = threadIdx.x; i < NB; i += blockDim.x) v += g_partial[i];
    float tot = block_sum(v, red);
    if (threadIdx.x == 0) out[0] = 1e-4f * (tot / (float)NB);
}

// ------------------------------------------------------------------
extern "C" void kernel_launch(void* const* d_in, const int* in_sizes, int n_in,
                              void* d_out, int out_size) {
    (void)in_sizes; (void)n_in; (void)out_size;
    const float* cores = (const float*)d_in[0];
    float* out = (float*)d_out;

    static const int SMEM_TRIDIAG = (PACK + 3 * NDIM + 32) * (int)sizeof(float);
    cudaFuncSetAttribute(tridiag_kernel,
                         cudaFuncAttributeMaxDynamicSharedMemorySize, SMEM_TRIDIAG);

    dim3 ggrid(10, 1, NB);
    dim3 gblock(16, 16);
    gram_kernel<<<ggrid, gblock>>>(cores);
    tridiag_kernel<<<NB, 256, SMEM_TRIDIAG>>>();
    eig_kernel<<<NB, 256>>>();
    final_kernel<<<1, 128>>>(out);
}

// round 3
// speedup vs baseline: 2.9453x; 2.9453x over previous
#include <cuda_runtime.h>
#include <cuda_bf16.h>
#include <cstdint>

#define NB   127
#define KD   1024
#define ND   256
#define NUPD 11
#define MSZ  ((size_t)ND * ND)      // 65536

static __device__ __align__(256) __nv_bfloat16 g_Xt[(size_t)NB * ND * KD]; // [b][i][k]
static __device__ __align__(256) float          g_G [(size_t)NB * MSZ];    // Gram, later P
static __device__ __align__(256) __nv_bfloat16  g_A [(size_t)NB * MSZ];    // A = G/c
static __device__ __align__(256) __nv_bfloat16  g_Y [2][(size_t)NB * MSZ];
static __device__ __align__(256) __nv_bfloat16  g_Z [2][(size_t)NB * MSZ];
static __device__ __align__(256) __nv_bfloat16  g_T [(size_t)NB * MSZ];
static __device__ float g_c[NB];
static __device__ float g_S[NB];

// ------------------------------------------------------------------ helpers
__device__ __forceinline__ uint32_t sptr(const void* p) {
    uint32_t a;
    asm("{ .reg .u64 t; cvta.to.shared.u64 t, %1; cvt.u32.u64 %0, t; }"
        : "=r"(a) : "l"(p));
    return a;
}
#define CP_ASYNC(dst, src) \
    asm volatile("cp.async.cg.shared.global [%0], [%1], 16;" :: "r"(dst), "l"(src))
#define CP_COMMIT() asm volatile("cp.async.commit_group;" ::: "memory")
#define CP_WAIT(n)  asm volatile("cp.async.wait_group %0;" :: "n"(n) : "memory")

__device__ __forceinline__ void ldsm4(uint32_t* r, uint32_t a) {
    asm volatile("ldmatrix.sync.aligned.m8n8.x4.shared.b16 {%0,%1,%2,%3}, [%4];"
                 : "=r"(r[0]), "=r"(r[1]), "=r"(r[2]), "=r"(r[3]) : "r"(a));
}
__device__ __forceinline__ void mma16816(float* d, const uint32_t* a, const uint32_t* b) {
    asm volatile("mma.sync.aligned.m16n8k16.row.col.f32.bf16.bf16.f32 "
                 "{%0,%1,%2,%3}, {%4,%5,%6,%7}, {%8,%9}, {%0,%1,%2,%3};"
                 : "+f"(d[0]), "+f"(d[1]), "+f"(d[2]), "+f"(d[3])
                 : "r"(a[0]), "r"(a[1]), "r"(a[2]), "r"(a[3]), "r"(b[0]), "r"(b[1]));
}

__device__ __forceinline__ float warp_sum(float v) {
#pragma unroll
    for (int o = 16; o > 0; o >>= 1) v += __shfl_xor_sync(0xffffffffu, v, o);
    return v;
}
__device__ float block_sum(float v, float* red) {
    int lane = threadIdx.x & 31, w = threadIdx.x >> 5;
    int nw = (blockDim.x + 31) >> 5;
    v = warp_sum(v);
    if (lane == 0) red[w] = v;
    __syncthreads();
    if (w == 0) {
        float t = (lane < nw) ? red[lane] : 0.f;
        t = warp_sum(t);
        if (lane == 0) red[0] = t;
    }
    __syncthreads();
    float r = red[0];
    __syncthreads();
    return r;
}

// ------------------------------------------------------------------ convert: X fp32 -> Xt bf16 (transposed)
__global__ void convert_kernel(const float* __restrict__ X) {
    __shared__ float tile[32][33];
    int b = blockIdx.z;
    int k0 = blockIdx.x * 32, i0 = blockIdx.y * 32;
    int tx = threadIdx.x, ty = threadIdx.y;
    const float* Xb = X + (size_t)b * KD * ND;
#pragma unroll
    for (int r = 0; r < 32; r += 8)
        tile[ty + r][tx] = Xb[(size_t)(k0 + ty + r) * ND + i0 + tx];
    __syncthreads();
#pragma unroll
    for (int r = 0; r < 32; r += 8)
        g_Xt[((size_t)b * ND + i0 + ty + r) * KD + k0 + tx] =
            __float2bfloat16(tile[tx][ty + r]);
}

// ------------------------------------------------------------------ generic GEMM: D = A * B^T (A,B row-major [rows][kk])
// CTA tile 128x128, out 256x256 per bond (grid.x 4 tiles, or 8 for dual launch)
// mode 0: store D fp32 ; mode 1: store (3I-D)/2 bf16 ; mode 2: store D bf16
#define SMEM_GEMM 65536

__global__ __launch_bounds__(256, 2)
void gemm_k(const __nv_bfloat16* __restrict__ A0, const __nv_bfloat16* __restrict__ B0,
            void* __restrict__ O0,
            const __nv_bfloat16* __restrict__ A1, const __nv_bfloat16* __restrict__ B1,
            void* __restrict__ O1,
            int kk, size_t aStr, size_t bStr, int mode)
{
    extern __shared__ char smraw[];
    const int b = blockIdx.y;
    const int second = (blockIdx.x >= 4);
    const int tix = blockIdx.x & 3;
    const int mt = tix >> 1, nt = tix & 1;

    const __nv_bfloat16* A = (second ? A1 : A0) + (size_t)b * aStr + (size_t)(mt * 128) * kk;
    const __nv_bfloat16* B = (second ? B1 : B0) + (size_t)b * bStr + (size_t)(nt * 128) * kk;

    uint32_t sA = sptr(smraw);        // 2 stages x 16KB
    uint32_t sB = sA + 32768;         // 2 stages x 16KB

    const int tid = threadIdx.x, lane = tid & 31, wid = tid >> 5;
    const int wm = wid >> 2, wn = wid & 3;

    float acc[4][4][4];
#pragma unroll
    for (int i = 0; i < 4; i++)
#pragma unroll
        for (int j = 0; j < 4; j++)
#pragma unroll
            for (int r = 0; r < 4; r++) acc[i][j][r] = 0.f;

    const int nc = kk >> 6;

    auto issue = [&](int c) {
        int s = c & 1;
        const __nv_bfloat16* Ag = A + c * 64;
        const __nv_bfloat16* Bg = B + c * 64;
#pragma unroll
        for (int q = 0; q < 4; q++) {
            int id = tid + q * 256;
            int r = id >> 3, u = id & 7;
            uint32_t off = (uint32_t)(r * 128 + u * 16);
            off ^= (off >> 3) & 0x70u;
            CP_ASYNC(sA + s * 16384 + off, Ag + (size_t)r * kk + u * 8);
            CP_ASYNC(sB + s * 16384 + off, Bg + (size_t)r * kk + u * 8);
        }
        CP_COMMIT();
    };

    issue(0);
    for (int c = 0; c < nc; c++) {
        if (c + 1 < nc) { issue(c + 1); CP_WAIT(1); }
        else            { CP_WAIT(0); }
        __syncthreads();
        int s = c & 1;
        uint32_t aBase = sA + s * 16384;
        uint32_t bBase = sB + s * 16384;
#pragma unroll
        for (int ks = 0; ks < 4; ks++) {
            uint32_t afr[4][4], bfr[4][2];
            int mx = lane >> 3;
#pragma unroll
            for (int mi = 0; mi < 4; mi++) {
                int mrow = wm * 64 + mi * 16 + (mx & 1) * 8 + (lane & 7);
                int kb = ks * 32 + (mx >> 1) * 16;
                uint32_t off = (uint32_t)(mrow * 128 + kb);
                off ^= (off >> 3) & 0x70u;
                ldsm4(afr[mi], aBase + off);
            }
#pragma unroll
            for (int nj = 0; nj < 2; nj++) {
                int nrow = wn * 32 + nj * 16 + (mx >> 1) * 8 + (lane & 7);
                int kb = ks * 32 + (mx & 1) * 16;
                uint32_t off = (uint32_t)(nrow * 128 + kb);
                off ^= (off >> 3) & 0x70u;
                uint32_t r4[4];
                ldsm4(r4, bBase + off);
                bfr[nj * 2][0] = r4[0]; bfr[nj * 2][1] = r4[1];
                bfr[nj * 2 + 1][0] = r4[2]; bfr[nj * 2 + 1][1] = r4[3];
            }
#pragma unroll
            for (int mi = 0; mi < 4; mi++)
#pragma unroll
                for (int ni = 0; ni < 4; ni++)
                    mma16816(acc[mi][ni], afr[mi], bfr[ni]);
        }
        __syncthreads();
    }

    // epilogue
    int gmb = mt * 128 + wm * 64;
    int gnb = nt * 128 + wn * 32;
    if (mode == 0) {
        float* Og = (float*)(second ? O1 : O0) + (size_t)b * MSZ;
#pragma unroll
        for (int mi = 0; mi < 4; mi++)
#pragma unroll
            for (int ni = 0; ni < 4; ni++) {
                int gm = gmb + mi * 16 + (lane >> 2);
                int gn = gnb + ni * 8 + (lane & 3) * 2;
                *(float2*)(Og + (size_t)gm * ND + gn) =
                    make_float2(acc[mi][ni][0], acc[mi][ni][1]);
                *(float2*)(Og + (size_t)(gm + 8) * ND + gn) =
                    make_float2(acc[mi][ni][2], acc[mi][ni][3]);
            }
    } else {
        __nv_bfloat16* Og = (__nv_bfloat16*)(second ? O1 : O0) + (size_t)b * MSZ;
#pragma unroll
        for (int mi = 0; mi < 4; mi++)
#pragma unroll
            for (int ni = 0; ni < 4; ni++) {
                int gm = gmb + mi * 16 + (lane >> 2);
                int gn = gnb + ni * 8 + (lane & 3) * 2;
                float d0 = acc[mi][ni][0], d1 = acc[mi][ni][1];
                float d2 = acc[mi][ni][2], d3 = acc[mi][ni][3];
                if (mode == 1) {
                    d0 = (((gn     == gm    ) ? 3.f : 0.f) - d0) * 0.5f;
                    d1 = (((gn + 1 == gm    ) ? 3.f : 0.f) - d1) * 0.5f;
                    d2 = (((gn     == gm + 8) ? 3.f : 0.f) - d2) * 0.5f;
                    d3 = (((gn + 1 == gm + 8) ? 3.f : 0.f) - d3) * 0.5f;
                }
                __nv_bfloat162 p0, p1;
                p0.x = __float2bfloat16(d0); p0.y = __float2bfloat16(d1);
                p1.x = __float2bfloat16(d2); p1.y = __float2bfloat16(d3);
                *(__nv_bfloat162*)(Og + (size_t)gm * ND + gn) = p0;
                *(__nv_bfloat162*)(Og + (size_t)(gm + 8) * ND + gn) = p1;
            }
    }
}

// ------------------------------------------------------------------ power iteration -> c = 1.3 * rayleigh(lambda_max)
__global__ void powc_kernel() {
    __shared__ float v[ND];
    __shared__ float red[32];
    int b = blockIdx.x, t = threadIdx.x;
    const float* G = g_G + (size_t)b * MSZ;
    v[t] = 1.f;
    __syncthreads();
    float w = 0.f;
    for (int it = 0; it < 4; it++) {
        const float4* row = (const float4*)(G + (size_t)t * ND);
        float a0 = 0.f;
#pragma unroll 8
        for (int j = 0; j < 64; j++) {
            float4 g = row[j];
            a0 += g.x * v[4 * j] + g.y * v[4 * j + 1] + g.z * v[4 * j + 2] + g.w * v[4 * j + 3];
        }
        w = a0;
        __syncthreads();
        if (it < 3) { v[t] = w; __syncthreads(); }
    }
    float vw = block_sum(v[t] * w, red);
    float vv = block_sum(v[t] * v[t], red);
    if (t == 0) g_c[b] = 1.3f * (vw / vv);
}

// ------------------------------------------------------------------ setup: A = G/c (bf16), Y0 = A, Z0 = I
__global__ void setup_kernel() {
    int b = blockIdx.x, t = threadIdx.x;
    float inv = 1.f / g_c[b];
    const float* G = g_G + (size_t)b * MSZ;
    __nv_bfloat16* A = g_A + (size_t)b * MSZ;
    __nv_bfloat16* Y = g_Y[0] + (size_t)b * MSZ;
    __nv_bfloat16* Z = g_Z[0] + (size_t)b * MSZ;
    for (int r = 0; r < ND; r++) {
        __nv_bfloat16 h = __float2bfloat16(G[(size_t)r * ND + t] * inv);
        A[(size_t)r * ND + t] = h;
        Y[(size_t)r * ND + t] = h;
        Z[(size_t)r * ND + t] = __float2bfloat16((r == t) ? 1.f : 0.f);
    }
}

// ------------------------------------------------------------------ refine: S_b = sqrt(c)*(tr(Y) + tr(Z*(A - P))/2), P in g_G
#define RS_PAD 258
__global__ void refine_kernel(const __nv_bfloat16* __restrict__ Yc,
                              const __nv_bfloat16* __restrict__ Zc) {
    extern __shared__ __nv_bfloat16 Zs[];   // [ND][RS_PAD]
    __shared__ float red[32];
    int b = blockIdx.x, t = threadIdx.x;
    const __nv_bfloat16* Z = Zc + (size_t)b * MSZ;
    for (int r = 0; r < ND; r++) Zs[(size_t)r * RS_PAD + t] = Z[(size_t)r * ND + t];
    __syncthreads();
    const __nv_bfloat16* A = g_A + (size_t)b * MSZ;
    const float* P = g_G + (size_t)b * MSZ;
    float corr = 0.f;
    for (int k = 0; k < ND; k++) {
        float e = __bfloat162float(A[(size_t)k * ND + t]) - P[(size_t)k * ND + t];
        corr += __bfloat162float(Zs[(size_t)t * RS_PAD + k]) * e;
    }
    float trY = __bfloat162float(Yc[(size_t)b * MSZ + (size_t)t * ND + t]);
    float c1 = block_sum(corr, red);
    float c2 = block_sum(trY, red);
    if (t == 0) g_S[b] = sqrtf(g_c[b]) * (c2 + 0.5f * c1);
}

__global__ void final_kernel(float* __restrict__ out) {
    __shared__ float red[32];
    float v = 0.f;
    for (int i = threadIdx.x; i < NB; i += blockDim.x) v += g_S[i];
    float tot = block_sum(v, red);
    if (threadIdx.x == 0) out[0] = 1e-4f * (tot / (float)NB);
}

// ------------------------------------------------------------------
extern "C" void kernel_launch(void* const* d_in, const int* in_sizes, int n_in,
                              void* d_out, int out_size) {
    (void)in_sizes; (void)n_in; (void)out_size;
    const float* cores = (const float*)d_in[0];
    float* out = (float*)d_out;

    cudaFuncSetAttribute(gemm_k, cudaFuncAttributeMaxDynamicSharedMemorySize, SMEM_GEMM);
    cudaFuncSetAttribute(refine_kernel, cudaFuncAttributeMaxDynamicSharedMemorySize,
                         ND * RS_PAD * (int)sizeof(__nv_bfloat16));

    void *xt_, *gg_, *aa_, *y_, *z_, *tt_;
    cudaGetSymbolAddress(&xt_, g_Xt);
    cudaGetSymbolAddress(&gg_, g_G);
    cudaGetSymbolAddress(&aa_, g_A);
    cudaGetSymbolAddress(&y_,  g_Y);
    cudaGetSymbolAddress(&z_,  g_Z);
    cudaGetSymbolAddress(&tt_, g_T);
    const __nv_bfloat16* Xt = (const __nv_bfloat16*)xt_;
    float* G = (float*)gg_;
    const __nv_bfloat16* A = (const __nv_bfloat16*)aa_;
    __nv_bfloat16* Y[2] = { (__nv_bfloat16*)y_, (__nv_bfloat16*)y_ + NB * MSZ };
    __nv_bfloat16* Z[2] = { (__nv_bfloat16*)z_, (__nv_bfloat16*)z_ + NB * MSZ };
    __nv_bfloat16* T = (__nv_bfloat16*)tt_;
    (void)A;

    convert_kernel<<<dim3(KD / 32, ND / 32, NB), dim3(32, 8)>>>(cores);

    // Gram: G = Xt * Xt^T (fp32)
    gemm_k<<<dim3(4, NB), 256, SMEM_GEMM>>>(Xt, Xt, G, Xt, Xt, G,
                                            KD, (size_t)ND * KD, (size_t)ND * KD, 0);
    powc_kernel<<<NB, 256>>>();
    setup_kernel<<<NB, 256>>>();

    int cur = 0;
    for (int t = 0; t < NUPD; t++) {
        // T = (3I - Z*Y^T)/2
        gemm_k<<<dim3(4, NB), 256, SMEM_GEMM>>>(Z[cur], Y[cur], T, Z[cur], Y[cur], T,
                                                ND, MSZ, MSZ, 1);
        // Y' = Y*T^T  (tiles 0-3) ; Z' = T*Z^T (tiles 4-7)
        gemm_k<<<dim3(8, NB), 256, SMEM_GEMM>>>(Y[cur], T, Y[cur ^ 1],
                                                T, Z[cur], Z[cur ^ 1],
                                                ND, MSZ, MSZ, 2);
        cur ^= 1;
    }

    // P = Y*Y^T (fp32, reuse g_G)
    gemm_k<<<dim3(4, NB), 256, SMEM_GEMM>>>(Y[cur], Y[cur], G, Y[cur], Y[cur], G,
                                            ND, MSZ, MSZ, 0);
    refine_kernel<<<NB, 256, ND * RS_PAD * sizeof(__nv_bfloat16)>>>(Y[cur], Z[cur]);
    final_kernel<<<1, 128>>>(out);
}

// round 5
// speedup vs baseline: 5.1758x; 1.7573x over previous
#include <cuda_runtime.h>
#include <cuda_bf16.h>
#include <cstdint>

#define NB    127
#define KD    1024
#define ND    256
#define NITER 5                 // loop NS updates (6 total with fused first)
#define MSZ   ((size_t)ND * ND)

static __device__ __align__(256) __nv_bfloat16 g_Xt[(size_t)NB * ND * KD]; // [b][i][k]
static __device__ __align__(256) float          g_G [(size_t)NB * MSZ];    // Gram, then P=YY^T
static __device__ __align__(256) __nv_bfloat16  g_A [(size_t)NB * MSZ];
static __device__ __align__(256) __nv_bfloat16  g_Y [2][(size_t)NB * MSZ];
static __device__ __align__(256) __nv_bfloat16  g_Z [2][(size_t)NB * MSZ];
static __device__ __align__(256) __nv_bfloat16  g_T [(size_t)NB * MSZ];
static __device__ float g_c[NB];
static __device__ float g_S[NB];

// ------------------------------------------------------------------ helpers
__device__ __forceinline__ uint32_t sptr(const void* p) {
    uint32_t a;
    asm("{ .reg .u64 t; cvta.to.shared.u64 t, %1; cvt.u32.u64 %0, t; }"
        : "=r"(a) : "l"(p));
    return a;
}
#define CP_ASYNC(dst, src) \
    asm volatile("cp.async.cg.shared.global [%0], [%1], 16;" :: "r"(dst), "l"(src))
#define CP_COMMIT() asm volatile("cp.async.commit_group;" ::: "memory")
#define CP_WAIT(n)  asm volatile("cp.async.wait_group %0;" :: "n"(n) : "memory")

__device__ __forceinline__ void ldsm4(uint32_t* r, uint32_t a) {
    asm volatile("ldmatrix.sync.aligned.m8n8.x4.shared.b16 {%0,%1,%2,%3}, [%4];"
                 : "=r"(r[0]), "=r"(r[1]), "=r"(r[2]), "=r"(r[3]) : "r"(a));
}
__device__ __forceinline__ void mma16816(float* d, const uint32_t* a, const uint32_t* b) {
    asm volatile("mma.sync.aligned.m16n8k16.row.col.f32.bf16.bf16.f32 "
                 "{%0,%1,%2,%3}, {%4,%5,%6,%7}, {%8,%9}, {%0,%1,%2,%3};"
                 : "+f"(d[0]), "+f"(d[1]), "+f"(d[2]), "+f"(d[3])
                 : "r"(a[0]), "r"(a[1]), "r"(a[2]), "r"(a[3]), "r"(b[0]), "r"(b[1]));
}

__device__ __forceinline__ float warp_sum(float v) {
#pragma unroll
    for (int o = 16; o > 0; o >>= 1) v += __shfl_xor_sync(0xffffffffu, v, o);
    return v;
}
__device__ float block_sum(float v, float* red) {
    int lane = threadIdx.x & 31, w = threadIdx.x >> 5;
    int nw = (blockDim.x + 31) >> 5;
    v = warp_sum(v);
    if (lane == 0) red[w] = v;
    __syncthreads();
    if (w == 0) {
        float t = (lane < nw) ? red[lane] : 0.f;
        t = warp_sum(t);
        if (lane == 0) red[0] = t;
    }
    __syncthreads();
    float r = red[0];
    __syncthreads();
    return r;
}

// ------------------------------------------------------------------ convert: X fp32 -> Xt bf16 (transposed)
__global__ void convert_kernel(const float* __restrict__ X) {
    __shared__ float tile[32][33];
    int b = blockIdx.z;
    int k0 = blockIdx.x * 32, i0 = blockIdx.y * 32;
    int tx = threadIdx.x, ty = threadIdx.y;
    const float* Xb = X + (size_t)b * KD * ND;
#pragma unroll
    for (int r = 0; r < 32; r += 8)
        tile[ty + r][tx] = Xb[(size_t)(k0 + ty + r) * ND + i0 + tx];
    __syncthreads();
#pragma unroll
    for (int r = 0; r < 32; r += 8)
        g_Xt[((size_t)b * ND + i0 + ty + r) * KD + k0 + tx] =
            __float2bfloat16(tile[tx][ty + r]);
}

// ------------------------------------------------------------------ templated GEMM: D = A * B^T
// CTA tile 128x128; grid.x=4 (single problem) or 8 (dual problems).
// MODE 0: store fp32 ; MODE 1: store (3I-D)/2 bf16 ; MODE 2: store D bf16
#define SMEM_GEMM 65536

template<int KK, int MODE>
__global__ __launch_bounds__(256, 2)
void gemm_t(const __nv_bfloat16* __restrict__ A0, const __nv_bfloat16* __restrict__ B0,
            void* __restrict__ O0,
            const __nv_bfloat16* __restrict__ A1, const __nv_bfloat16* __restrict__ B1,
            void* __restrict__ O1, size_t aStr, size_t bStr)
{
    extern __shared__ char smraw[];
    const int b = blockIdx.y;
    const int second = (blockIdx.x >= 4) ? 1 : 0;
    const int tix = blockIdx.x & 3;
    const int mt = tix >> 1, nt = tix & 1;

    const __nv_bfloat16* A = (second ? A1 : A0) + (size_t)b * aStr + (size_t)(mt * 128) * KK;
    const __nv_bfloat16* B = (second ? B1 : B0) + (size_t)b * bStr + (size_t)(nt * 128) * KK;

    uint32_t sA = sptr(smraw);
    uint32_t sB = sA + 32768;

    const int tid = threadIdx.x, lane = tid & 31, wid = tid >> 5;
    const int wm = wid >> 2, wn = wid & 3;
    const int mx = lane >> 3;

    uint32_t baseA[4], xorA[4], baseB[2], xorB[2];
#pragma unroll
    for (int mi = 0; mi < 4; mi++) {
        int row = wm * 64 + mi * 16 + (mx & 1) * 8 + (lane & 7);
        baseA[mi] = (uint32_t)(row * 128 + (mx >> 1) * 16);
        xorA[mi]  = (uint32_t)((row & 7) << 4);
    }
#pragma unroll
    for (int nj = 0; nj < 2; nj++) {
        int row = wn * 32 + nj * 16 + (mx >> 1) * 8 + (lane & 7);
        baseB[nj] = (uint32_t)(row * 128 + (mx & 1) * 16);
        xorB[nj]  = (uint32_t)((row & 7) << 4);
    }

    float acc[4][4][4];
#pragma unroll
    for (int i = 0; i < 4; i++)
#pragma unroll
        for (int j = 0; j < 4; j++)
#pragma unroll
            for (int r = 0; r < 4; r++) acc[i][j][r] = 0.f;

    constexpr int nc = KK / 64;

    auto issue = [&](int c) {
        int s = c & 1;
        const __nv_bfloat16* Ag = A + c * 64;
        const __nv_bfloat16* Bg = B + c * 64;
#pragma unroll
        for (int q = 0; q < 4; q++) {
            int id = tid + q * 256;
            int r = id >> 3, u = id & 7;
            uint32_t off = (uint32_t)(r * 128 + u * 16);
            off ^= (off >> 3) & 0x70u;
            CP_ASYNC(sA + s * 16384 + off, Ag + (size_t)r * KK + u * 8);
            CP_ASYNC(sB + s * 16384 + off, Bg + (size_t)r * KK + u * 8);
        }
        CP_COMMIT();
    };

    issue(0);
#pragma unroll 4
    for (int c = 0; c < nc; c++) {
        if (c + 1 < nc) { issue(c + 1); CP_WAIT(1); }
        else            { CP_WAIT(0); }
        __syncthreads();
        uint32_t aB = sA + (uint32_t)(c & 1) * 16384;
        uint32_t bB = sB + (uint32_t)(c & 1) * 16384;
#pragma unroll
        for (int ks = 0; ks < 4; ks++) {
            uint32_t afr[4][4], bfr[4][2];
#pragma unroll
            for (int mi = 0; mi < 4; mi++)
                ldsm4(afr[mi], aB + ((baseA[mi] + ks * 32) ^ xorA[mi]));
#pragma unroll
            for (int nj = 0; nj < 2; nj++) {
                uint32_t r4[4];
                ldsm4(r4, bB + ((baseB[nj] + ks * 32) ^ xorB[nj]));
                bfr[nj * 2][0] = r4[0]; bfr[nj * 2][1] = r4[1];
                bfr[nj * 2 + 1][0] = r4[2]; bfr[nj * 2 + 1][1] = r4[3];
            }
#pragma unroll
            for (int mi = 0; mi < 4; mi++)
#pragma unroll
                for (int ni = 0; ni < 4; ni++)
                    mma16816(acc[mi][ni], afr[mi], bfr[ni]);
        }
        __syncthreads();
    }

    int gmb = mt * 128 + wm * 64;
    int gnb = nt * 128 + wn * 32;
    if (MODE == 0) {
        float* Og = (float*)(second ? O1 : O0) + (size_t)b * MSZ;
#pragma unroll
        for (int mi = 0; mi < 4; mi++)
#pragma unroll
            for (int ni = 0; ni < 4; ni++) {
                int gm = gmb + mi * 16 + (lane >> 2);
                int gn = gnb + ni * 8 + (lane & 3) * 2;
                *(float2*)(Og + (size_t)gm * ND + gn) =
                    make_float2(acc[mi][ni][0], acc[mi][ni][1]);
                *(float2*)(Og + (size_t)(gm + 8) * ND + gn) =
                    make_float2(acc[mi][ni][2], acc[mi][ni][3]);
            }
    } else {
        __nv_bfloat16* Og = (__nv_bfloat16*)(second ? O1 : O0) + (size_t)b * MSZ;
#pragma unroll
        for (int mi = 0; mi < 4; mi++)
#pragma unroll
            for (int ni = 0; ni < 4; ni++) {
                int gm = gmb + mi * 16 + (lane >> 2);
                int gn = gnb + ni * 8 + (lane & 3) * 2;
                float d0 = acc[mi][ni][0], d1 = acc[mi][ni][1];
                float d2 = acc[mi][ni][2], d3 = acc[mi][ni][3];
                if (MODE == 1) {
                    d0 = (((gn     == gm    ) ? 3.f : 0.f) - d0) * 0.5f;
                    d1 = (((gn + 1 == gm    ) ? 3.f : 0.f) - d1) * 0.5f;
                    d2 = (((gn     == gm + 8) ? 3.f : 0.f) - d2) * 0.5f;
                    d3 = (((gn + 1 == gm + 8) ? 3.f : 0.f) - d3) * 0.5f;
                }
                __nv_bfloat162 p0, p1;
                p0.x = __float2bfloat16(d0); p0.y = __float2bfloat16(d1);
                p1.x = __float2bfloat16(d2); p1.y = __float2bfloat16(d3);
                *(__nv_bfloat162*)(Og + (size_t)gm * ND + gn) = p0;
                *(__nv_bfloat162*)(Og + (size_t)(gm + 8) * ND + gn) = p1;
            }
    }
}

// ------------------------------------------------------------------ power iteration -> c = rayleigh(lambda_max)
__global__ void powc_kernel() {
    __shared__ float v[ND];
    __shared__ float red[32];
    int b = blockIdx.x, t = threadIdx.x;
    const float* G = g_G + (size_t)b * MSZ;
    v[t] = 1.f;
    __syncthreads();
    float w = 0.f;
    for (int it = 0; it < 5; it++) {
        const float4* row = (const float4*)(G + (size_t)t * ND);
        float a0 = 0.f;
#pragma unroll 8
        for (int j = 0; j < 64; j++) {
            float4 g = row[j];
            a0 += g.x * v[4 * j] + g.y * v[4 * j + 1] + g.z * v[4 * j + 2] + g.w * v[4 * j + 3];
        }
        w = a0;
        __syncthreads();
        if (it < 4) { v[t] = w; __syncthreads(); }
    }
    float vw = block_sum(v[t] * w, red);
    float vv = block_sum(v[t] * v[t], red);
    if (t == 0) g_c[b] = vw / vv;   // Rayleigh <= lambda_max; a in (0, ~1.1]
}

// ------------------------------------------------------------------ setup (wide): A=G/c bf16, T0=(3I-A)/2, Z1=T0
__global__ void setup_kernel() {
    int b = blockIdx.y;
    float inv = 1.f / g_c[b];
    const float* G = g_G + (size_t)b * MSZ;
    __nv_bfloat16* Ab = g_A + (size_t)b * MSZ;
    __nv_bfloat16* T0 = g_T + (size_t)b * MSZ;
    __nv_bfloat16* Z1 = g_Z[1] + (size_t)b * MSZ;
    int col4 = threadIdx.x & 63;
    int rsub = threadIdx.x >> 6;
#pragma unroll
    for (int j = 0; j < 8; j++) {
        int r = blockIdx.x * 32 + j * 4 + rsub;
        float4 g = *(const float4*)(G + (size_t)r * ND + col4 * 4);
        float a0 = g.x * inv, a1 = g.y * inv, a2 = g.z * inv, a3 = g.w * inv;
        int c0 = col4 * 4;
        float t0 = (((c0     == r) ? 3.f : 0.f) - a0) * 0.5f;
        float t1 = (((c0 + 1 == r) ? 3.f : 0.f) - a1) * 0.5f;
        float t2 = (((c0 + 2 == r) ? 3.f : 0.f) - a2) * 0.5f;
        float t3 = (((c0 + 3 == r) ? 3.f : 0.f) - a3) * 0.5f;
        __nv_bfloat162 ha0 = __floats2bfloat162_rn(a0, a1);
        __nv_bfloat162 ha1 = __floats2bfloat162_rn(a2, a3);
        __nv_bfloat162 ht0 = __floats2bfloat162_rn(t0, t1);
        __nv_bfloat162 ht1 = __floats2bfloat162_rn(t2, t3);
        uint2 ua = make_uint2(*(uint32_t*)&ha0, *(uint32_t*)&ha1);
        uint2 ut = make_uint2(*(uint32_t*)&ht0, *(uint32_t*)&ht1);
        *(uint2*)(Ab + (size_t)r * ND + c0) = ua;
        *(uint2*)(T0 + (size_t)r * ND + c0) = ut;
        *(uint2*)(Z1 + (size_t)r * ND + c0) = ut;
    }
}

// ------------------------------------------------------------------ refine: S = sqrt(c)*(trY + 0.5*<Z, A - P>), P fp32 in g_G
__global__ void refine_kernel(const __nv_bfloat16* __restrict__ Y,
                              const __nv_bfloat16* __restrict__ Z) {
    __shared__ float red[32];
    int b = blockIdx.x, t = threadIdx.x;
    const uint4*  Zp = (const uint4*)(Z + (size_t)b * MSZ);
    const uint4*  Ap = (const uint4*)(g_A + (size_t)b * MSZ);
    const float4* Pp = (const float4*)(g_G + (size_t)b * MSZ);
    float corr = 0.f;
#pragma unroll 4
    for (int i = 0; i < 32; i++) {
        int v = t + i * 256;
        uint4 zz = Zp[v], aa = Ap[v];
        float4 p0 = Pp[2 * v], p1 = Pp[2 * v + 1];
        const uint32_t* za = (const uint32_t*)&zz;
        const uint32_t* ab = (const uint32_t*)&aa;
        float pe[8] = {p0.x, p0.y, p0.z, p0.w, p1.x, p1.y, p1.z, p1.w};
#pragma unroll
        for (int k = 0; k < 4; k++) {
            float2 zf = __bfloat1622float2(*(const __nv_bfloat162*)&za[k]);
            float2 af = __bfloat1622float2(*(const __nv_bfloat162*)&ab[k]);
            corr += zf.x * (af.x - pe[2 * k]) + zf.y * (af.y - pe[2 * k + 1]);
        }
    }
    float trY = __bfloat162float(Y[(size_t)b * MSZ + (size_t)t * ND + t]);
    float sC = block_sum(corr, red);
    float sY = block_sum(trY, red);
    if (t == 0) g_S[b] = sqrtf(g_c[b]) * (sY + 0.5f * sC);
}

__global__ void final_kernel(float* __restrict__ out) {
    __shared__ float red[32];
    float v = 0.f;
    for (int i = threadIdx.x; i < NB; i += blockDim.x) v += g_S[i];
    float tot = block_sum(v, red);
    if (threadIdx.x == 0) out[0] = 1e-4f * (tot / (float)NB);
}

// ------------------------------------------------------------------
extern "C" void kernel_launch(void* const* d_in, const int* in_sizes, int n_in,
                              void* d_out, int out_size) {
    (void)in_sizes; (void)n_in; (void)out_size;
    const float* cores = (const float*)d_in[0];
    float* out = (float*)d_out;

    cudaFuncSetAttribute(gemm_t<1024, 0>, cudaFuncAttributeMaxDynamicSharedMemorySize, SMEM_GEMM);
    cudaFuncSetAttribute(gemm_t<256, 0>,  cudaFuncAttributeMaxDynamicSharedMemorySize, SMEM_GEMM);
    cudaFuncSetAttribute(gemm_t<256, 1>,  cudaFuncAttributeMaxDynamicSharedMemorySize, SMEM_GEMM);
    cudaFuncSetAttribute(gemm_t<256, 2>,  cudaFuncAttributeMaxDynamicSharedMemorySize, SMEM_GEMM);

    void *xt_, *gg_, *aa_, *y_, *z_, *tt_;
    cudaGetSymbolAddress(&xt_, g_Xt);
    cudaGetSymbolAddress(&gg_, g_G);
    cudaGetSymbolAddress(&aa_, g_A);
    cudaGetSymbolAddress(&y_,  g_Y);
    cudaGetSymbolAddress(&z_,  g_Z);
    cudaGetSymbolAddress(&tt_, g_T);
    const __nv_bfloat16* Xt = (const __nv_bfloat16*)xt_;
    float* G = (float*)gg_;
    const __nv_bfloat16* Ab = (const __nv_bfloat16*)aa_;
    __nv_bfloat16* Y[2] = { (__nv_bfloat16*)y_, (__nv_bfloat16*)y_ + NB * MSZ };
    __nv_bfloat16* Z[2] = { (__nv_bfloat16*)z_, (__nv_bfloat16*)z_ + NB * MSZ };
    __nv_bfloat16* T = (__nv_bfloat16*)tt_;

    convert_kernel<<<dim3(KD / 32, ND / 32, NB), dim3(32, 8)>>>(cores);

    // G = Xt * Xt^T (fp32)
    gemm_t<1024, 0><<<dim3(4, NB), 256, SMEM_GEMM>>>(Xt, Xt, G, Xt, Xt, G,
                                                     (size_t)ND * KD, (size_t)ND * KD);
    powc_kernel<<<NB, 256>>>();
    setup_kernel<<<dim3(8, NB), 256>>>();      // A, T0, Z1 (fused first update)

    // Y1 = A * T0^T  (update #1 completes)
    gemm_t<256, 2><<<dim3(4, NB), 256, SMEM_GEMM>>>(Ab, T, Y[1], Ab, T, Y[1], MSZ, MSZ);

    int cur = 1;
    for (int t = 0; t < NITER; t++) {
        gemm_t<256, 1><<<dim3(4, NB), 256, SMEM_GEMM>>>(Z[cur], Y[cur], T,
                                                        Z[cur], Y[cur], T, MSZ, MSZ);
        gemm_t<256, 2><<<dim3(8, NB), 256, SMEM_GEMM>>>(Y[cur], T, Y[cur ^ 1],
                                                        T, Z[cur], Z[cur ^ 1], MSZ, MSZ);
        cur ^= 1;
    }

    // P = Y*Y^T (fp32) for the first-order trace correction
    gemm_t<256, 0><<<dim3(4, NB), 256, SMEM_GEMM>>>(Y[cur], Y[cur], G,
                                                    Y[cur], Y[cur], G, MSZ, MSZ);
    refine_kernel<<<NB, 256>>>(Y[cur], Z[cur]);
    final_kernel<<<1, 128>>>(out);
}

// round 6
// speedup vs baseline: 5.8582x; 1.1318x over previous
#include <cuda_runtime.h>
#include <cuda_bf16.h>
#include <cstdint>

#define NB    127
#define KD    1024
#define ND    256
#define NITER 4                 // loop NS updates (5 total with fused first)
#define MSZ   ((size_t)ND * ND)

static __device__ __align__(256) __nv_bfloat16 g_Xt[(size_t)NB * ND * KD]; // [b][i][k]
static __device__ __align__(256) float          g_G [(size_t)NB * MSZ];    // Gram, then P=YY^T
static __device__ __align__(256) __nv_bfloat16  g_A [(size_t)NB * MSZ];
static __device__ __align__(256) __nv_bfloat16  g_Y [2][(size_t)NB * MSZ];
static __device__ __align__(256) __nv_bfloat16  g_Z [2][(size_t)NB * MSZ];
static __device__ __align__(256) __nv_bfloat16  g_T [(size_t)NB * MSZ];
static __device__ float g_c[NB];
static __device__ float g_S[NB];

// ------------------------------------------------------------------ helpers
__device__ __forceinline__ uint32_t sptr(const void* p) {
    uint32_t a;
    asm("{ .reg .u64 t; cvta.to.shared.u64 t, %1; cvt.u32.u64 %0, t; }"
        : "=r"(a) : "l"(p));
    return a;
}
#define CP_ASYNC(dst, src) \
    asm volatile("cp.async.cg.shared.global [%0], [%1], 16;" :: "r"(dst), "l"(src))
#define CP_COMMIT() asm volatile("cp.async.commit_group;" ::: "memory")
#define CP_WAIT(n)  asm volatile("cp.async.wait_group %0;" :: "n"(n) : "memory")

__device__ __forceinline__ void ldsm4(uint32_t* r, uint32_t a) {
    asm volatile("ldmatrix.sync.aligned.m8n8.x4.shared.b16 {%0,%1,%2,%3}, [%4];"
                 : "=r"(r[0]), "=r"(r[1]), "=r"(r[2]), "=r"(r[3]) : "r"(a));
}
__device__ __forceinline__ void mma16816(float* d, const uint32_t* a, const uint32_t* b) {
    asm volatile("mma.sync.aligned.m16n8k16.row.col.f32.bf16.bf16.f32 "
                 "{%0,%1,%2,%3}, {%4,%5,%6,%7}, {%8,%9}, {%0,%1,%2,%3};"
                 : "+f"(d[0]), "+f"(d[1]), "+f"(d[2]), "+f"(d[3])
                 : "r"(a[0]), "r"(a[1]), "r"(a[2]), "r"(a[3]), "r"(b[0]), "r"(b[1]));
}

__device__ __forceinline__ float warp_sum(float v) {
#pragma unroll
    for (int o = 16; o > 0; o >>= 1) v += __shfl_xor_sync(0xffffffffu, v, o);
    return v;
}
__device__ float block_sum(float v, float* red) {
    int lane = threadIdx.x & 31, w = threadIdx.x >> 5;
    int nw = (blockDim.x + 31) >> 5;
    v = warp_sum(v);
    if (lane == 0) red[w] = v;
    __syncthreads();
    if (w == 0) {
        float t = (lane < nw) ? red[lane] : 0.f;
        t = warp_sum(t);
        if (lane == 0) red[0] = t;
    }
    __syncthreads();
    float r = red[0];
    __syncthreads();
    return r;
}

// ------------------------------------------------------------------ convert: X fp32 -> Xt bf16 (transposed)
__global__ void convert_kernel(const float* __restrict__ X) {
    __shared__ float tile[32][33];
    int b = blockIdx.z;
    int k0 = blockIdx.x * 32, i0 = blockIdx.y * 32;
    int tx = threadIdx.x, ty = threadIdx.y;
    const float* Xb = X + (size_t)b * KD * ND;
#pragma unroll
    for (int r = 0; r < 32; r += 8)
        tile[ty + r][tx] = Xb[(size_t)(k0 + ty + r) * ND + i0 + tx];
    __syncthreads();
#pragma unroll
    for (int r = 0; r < 32; r += 8)
        g_Xt[((size_t)b * ND + i0 + ty + r) * KD + k0 + tx] =
            __float2bfloat16(tile[tx][ty + r]);
}

// ------------------------------------------------------------------ symmetric GEMM: D = A * B^T, D assumed symmetric.
// Computes only lower-tri CTA tiles {(0,0),(1,0),(1,1)}; tile (1,0) mirrors into (0,1).
// grid.x = 3 (single problem) or 6 (dual). MODE 0: fp32 ; 1: (3I-D)/2 bf16 ; 2: D bf16
#define SMEM_GEMM 65536

template<int KK, int MODE>
__global__ __launch_bounds__(256, 2)
void gemm_t(const __nv_bfloat16* __restrict__ A0, const __nv_bfloat16* __restrict__ B0,
            void* __restrict__ O0,
            const __nv_bfloat16* __restrict__ A1, const __nv_bfloat16* __restrict__ B1,
            void* __restrict__ O1, size_t aStr, size_t bStr)
{
    extern __shared__ char smraw[];
    const int b = blockIdx.y;
    const int second = (blockIdx.x >= 3) ? 1 : 0;
    const int tix = blockIdx.x - second * 3;
    const int mt = (tix + 1) >> 1, nt = tix >> 1;   // (0,0),(1,0),(1,1)
    const bool mirror = (tix == 1);

    const __nv_bfloat16* A = (second ? A1 : A0) + (size_t)b * aStr + (size_t)(mt * 128) * KK;
    const __nv_bfloat16* B = (second ? B1 : B0) + (size_t)b * bStr + (size_t)(nt * 128) * KK;

    uint32_t sA = sptr(smraw);
    uint32_t sB = sA + 32768;

    const int tid = threadIdx.x, lane = tid & 31, wid = tid >> 5;
    const int wm = wid >> 2, wn = wid & 3;
    const int mx = lane >> 3;

    uint32_t baseA[4], xorA[4], baseB[2], xorB[2];
#pragma unroll
    for (int mi = 0; mi < 4; mi++) {
        int row = wm * 64 + mi * 16 + (mx & 1) * 8 + (lane & 7);
        baseA[mi] = (uint32_t)(row * 128 + (mx >> 1) * 16);
        xorA[mi]  = (uint32_t)((row & 7) << 4);
    }
#pragma unroll
    for (int nj = 0; nj < 2; nj++) {
        int row = wn * 32 + nj * 16 + (mx >> 1) * 8 + (lane & 7);
        baseB[nj] = (uint32_t)(row * 128 + (mx & 1) * 16);
        xorB[nj]  = (uint32_t)((row & 7) << 4);
    }

    float acc[4][4][4];
#pragma unroll
    for (int i = 0; i < 4; i++)
#pragma unroll
        for (int j = 0; j < 4; j++)
#pragma unroll
            for (int r = 0; r < 4; r++) acc[i][j][r] = 0.f;

    constexpr int nc = KK / 64;

    auto issue = [&](int c) {
        int s = c & 1;
        const __nv_bfloat16* Ag = A + c * 64;
        const __nv_bfloat16* Bg = B + c * 64;
#pragma unroll
        for (int q = 0; q < 4; q++) {
            int id = tid + q * 256;
            int r = id >> 3, u = id & 7;
            uint32_t off = (uint32_t)(r * 128 + u * 16);
            off ^= (off >> 3) & 0x70u;
            CP_ASYNC(sA + s * 16384 + off, Ag + (size_t)r * KK + u * 8);
            CP_ASYNC(sB + s * 16384 + off, Bg + (size_t)r * KK + u * 8);
        }
        CP_COMMIT();
    };

    issue(0);
#pragma unroll 4
    for (int c = 0; c < nc; c++) {
        if (c + 1 < nc) { issue(c + 1); CP_WAIT(1); }
        else            { CP_WAIT(0); }
        __syncthreads();
        uint32_t aB = sA + (uint32_t)(c & 1) * 16384;
        uint32_t bB = sB + (uint32_t)(c & 1) * 16384;
#pragma unroll
        for (int ks = 0; ks < 4; ks++) {
            uint32_t afr[4][4], bfr[4][2];
#pragma unroll
            for (int mi = 0; mi < 4; mi++)
                ldsm4(afr[mi], aB + ((baseA[mi] + ks * 32) ^ xorA[mi]));
#pragma unroll
            for (int nj = 0; nj < 2; nj++) {
                uint32_t r4[4];
                ldsm4(r4, bB + ((baseB[nj] + ks * 32) ^ xorB[nj]));
                bfr[nj * 2][0] = r4[0]; bfr[nj * 2][1] = r4[1];
                bfr[nj * 2 + 1][0] = r4[2]; bfr[nj * 2 + 1][1] = r4[3];
            }
#pragma unroll
            for (int mi = 0; mi < 4; mi++)
#pragma unroll
                for (int ni = 0; ni < 4; ni++)
                    mma16816(acc[mi][ni], afr[mi], bfr[ni]);
        }
        __syncthreads();
    }

    int gmb = mt * 128 + wm * 64;
    int gnb = nt * 128 + wn * 32;
    if (MODE == 0) {
        float* Og = (float*)(second ? O1 : O0) + (size_t)b * MSZ;
#pragma unroll
        for (int mi = 0; mi < 4; mi++)
#pragma unroll
            for (int ni = 0; ni < 4; ni++) {
                int gm = gmb + mi * 16 + (lane >> 2);
                int gn = gnb + ni * 8 + (lane & 3) * 2;
                float d0 = acc[mi][ni][0], d1 = acc[mi][ni][1];
                float d2 = acc[mi][ni][2], d3 = acc[mi][ni][3];
                *(float2*)(Og + (size_t)gm * ND + gn) = make_float2(d0, d1);
                *(float2*)(Og + (size_t)(gm + 8) * ND + gn) = make_float2(d2, d3);
                if (mirror) {
                    Og[(size_t)gn * ND + gm] = d0;
                    Og[(size_t)(gn + 1) * ND + gm] = d1;
                    Og[(size_t)gn * ND + gm + 8] = d2;
                    Og[(size_t)(gn + 1) * ND + gm + 8] = d3;
                }
            }
    } else {
        __nv_bfloat16* Og = (__nv_bfloat16*)(second ? O1 : O0) + (size_t)b * MSZ;
#pragma unroll
        for (int mi = 0; mi < 4; mi++)
#pragma unroll
            for (int ni = 0; ni < 4; ni++) {
                int gm = gmb + mi * 16 + (lane >> 2);
                int gn = gnb + ni * 8 + (lane & 3) * 2;
                float d0 = acc[mi][ni][0], d1 = acc[mi][ni][1];
                float d2 = acc[mi][ni][2], d3 = acc[mi][ni][3];
                if (MODE == 1) {
                    d0 = (((gn     == gm    ) ? 3.f : 0.f) - d0) * 0.5f;
                    d1 = (((gn + 1 == gm    ) ? 3.f : 0.f) - d1) * 0.5f;
                    d2 = (((gn     == gm + 8) ? 3.f : 0.f) - d2) * 0.5f;
                    d3 = (((gn + 1 == gm + 8) ? 3.f : 0.f) - d3) * 0.5f;
                }
                __nv_bfloat16 h0 = __float2bfloat16(d0), h1 = __float2bfloat16(d1);
                __nv_bfloat16 h2 = __float2bfloat16(d2), h3 = __float2bfloat16(d3);
                __nv_bfloat162 p0, p1;
                p0.x = h0; p0.y = h1;
                p1.x = h2; p1.y = h3;
                *(__nv_bfloat162*)(Og + (size_t)gm * ND + gn) = p0;
                *(__nv_bfloat162*)(Og + (size_t)(gm + 8) * ND + gn) = p1;
                if (mirror) {
                    Og[(size_t)gn * ND + gm] = h0;
                    Og[(size_t)(gn + 1) * ND + gm] = h1;
                    Og[(size_t)gn * ND + gm + 8] = h2;
                    Og[(size_t)(gn + 1) * ND + gm + 8] = h3;
                }
            }
    }
}

// ------------------------------------------------------------------ power iteration -> c = rayleigh
__global__ void powc_kernel() {
    __shared__ float v[ND];
    __shared__ float red[32];
    int b = blockIdx.x, t = threadIdx.x;
    const float* G = g_G + (size_t)b * MSZ;
    v[t] = 1.f;
    __syncthreads();
    float w = 0.f;
    for (int it = 0; it < 5; it++) {
        const float4* row = (const float4*)(G + (size_t)t * ND);
        float a0 = 0.f;
#pragma unroll 8
        for (int j = 0; j < 64; j++) {
            float4 g = row[j];
            a0 += g.x * v[4 * j] + g.y * v[4 * j + 1] + g.z * v[4 * j + 2] + g.w * v[4 * j + 3];
        }
        w = a0;
        __syncthreads();
        if (it < 4) { v[t] = w; __syncthreads(); }
    }
    float vw = block_sum(v[t] * w, red);
    float vv = block_sum(v[t] * v[t], red);
    if (t == 0) g_c[b] = vw / vv;
}

// ------------------------------------------------------------------ setup: A=G/c bf16, T0=(3I-A)/2, Z1=T0
__global__ void setup_kernel() {
    int b = blockIdx.y;
    float inv = 1.f / g_c[b];
    const float* G = g_G + (size_t)b * MSZ;
    __nv_bfloat16* Ab = g_A + (size_t)b * MSZ;
    __nv_bfloat16* T0 = g_T + (size_t)b * MSZ;
    __nv_bfloat16* Z1 = g_Z[1] + (size_t)b * MSZ;
    int col4 = threadIdx.x & 63;
    int rsub = threadIdx.x >> 6;
#pragma unroll
    for (int j = 0; j < 8; j++) {
        int r = blockIdx.x * 32 + j * 4 + rsub;
        float4 g = *(const float4*)(G + (size_t)r * ND + col4 * 4);
        float a0 = g.x * inv, a1 = g.y * inv, a2 = g.z * inv, a3 = g.w * inv;
        int c0 = col4 * 4;
        float t0 = (((c0     == r) ? 3.f : 0.f) - a0) * 0.5f;
        float t1 = (((c0 + 1 == r) ? 3.f : 0.f) - a1) * 0.5f;
        float t2 = (((c0 + 2 == r) ? 3.f : 0.f) - a2) * 0.5f;
        float t3 = (((c0 + 3 == r) ? 3.f : 0.f) - a3) * 0.5f;
        __nv_bfloat162 ha0 = __floats2bfloat162_rn(a0, a1);
        __nv_bfloat162 ha1 = __floats2bfloat162_rn(a2, a3);
        __nv_bfloat162 ht0 = __floats2bfloat162_rn(t0, t1);
        __nv_bfloat162 ht1 = __floats2bfloat162_rn(t2, t3);
        uint2 ua = make_uint2(*(uint32_t*)&ha0, *(uint32_t*)&ha1);
        uint2 ut = make_uint2(*(uint32_t*)&ht0, *(uint32_t*)&ht1);
        *(uint2*)(Ab + (size_t)r * ND + c0) = ua;
        *(uint2*)(T0 + (size_t)r * ND + c0) = ut;
        *(uint2*)(Z1 + (size_t)r * ND + c0) = ut;
    }
}

// ------------------------------------------------------------------ refine: S = sqrt(c)*(trY + 0.5*<Z, A - P>)
__global__ void refine_kernel(const __nv_bfloat16* __restrict__ Y,
                              const __nv_bfloat16* __restrict__ Z) {
    __shared__ float red[32];
    int b = blockIdx.x, t = threadIdx.x;
    const uint4*  Zp = (const uint4*)(Z + (size_t)b * MSZ);
    const uint4*  Ap = (const uint4*)(g_A + (size_t)b * MSZ);
    const float4* Pp = (const float4*)(g_G + (size_t)b * MSZ);
    float corr = 0.f;
#pragma unroll 4
    for (int i = 0; i < 32; i++) {
        int v = t + i * 256;
        uint4 zz = Zp[v], aa = Ap[v];
        float4 p0 = Pp[2 * v], p1 = Pp[2 * v + 1];
        const uint32_t* za = (const uint32_t*)&zz;
        const uint32_t* ab = (const uint32_t*)&aa;
        float pe[8] = {p0.x, p0.y, p0.z, p0.w, p1.x, p1.y, p1.z, p1.w};
#pragma unroll
        for (int k = 0; k < 4; k++) {
            float2 zf = __bfloat1622float2(*(const __nv_bfloat162*)&za[k]);
            float2 af = __bfloat1622float2(*(const __nv_bfloat162*)&ab[k]);
            corr += zf.x * (af.x - pe[2 * k]) + zf.y * (af.y - pe[2 * k + 1]);
        }
    }
    float trY = __bfloat162float(Y[(size_t)b * MSZ + (size_t)t * ND + t]);
    float sC = block_sum(corr, red);
    float sY = block_sum(trY, red);
    if (t == 0) g_S[b] = sqrtf(g_c[b]) * (sY + 0.5f * sC);
}

__global__ void final_kernel(float* __restrict__ out) {
    __shared__ float red[32];
    float v = 0.f;
    for (int i = threadIdx.x; i < NB; i += blockDim.x) v += g_S[i];
    float tot = block_sum(v, red);
    if (threadIdx.x == 0) out[0] = 1e-4f * (tot / (float)NB);
}

// ------------------------------------------------------------------
extern "C" void kernel_launch(void* const* d_in, const int* in_sizes, int n_in,
                              void* d_out, int out_size) {
    (void)in_sizes; (void)n_in; (void)out_size;
    const float* cores = (const float*)d_in[0];
    float* out = (float*)d_out;

    cudaFuncSetAttribute(gemm_t<1024, 0>, cudaFuncAttributeMaxDynamicSharedMemorySize, SMEM_GEMM);
    cudaFuncSetAttribute(gemm_t<256, 0>,  cudaFuncAttributeMaxDynamicSharedMemorySize, SMEM_GEMM);
    cudaFuncSetAttribute(gemm_t<256, 1>,  cudaFuncAttributeMaxDynamicSharedMemorySize, SMEM_GEMM);
    cudaFuncSetAttribute(gemm_t<256, 2>,  cudaFuncAttributeMaxDynamicSharedMemorySize, SMEM_GEMM);

    void *xt_, *gg_, *aa_, *y_, *z_, *tt_;
    cudaGetSymbolAddress(&xt_, g_Xt);
    cudaGetSymbolAddress(&gg_, g_G);
    cudaGetSymbolAddress(&aa_, g_A);
    cudaGetSymbolAddress(&y_,  g_Y);
    cudaGetSymbolAddress(&z_,  g_Z);
    cudaGetSymbolAddress(&tt_, g_T);
    const __nv_bfloat16* Xt = (const __nv_bfloat16*)xt_;
    float* G = (float*)gg_;
    const __nv_bfloat16* Ab = (const __nv_bfloat16*)aa_;
    __nv_bfloat16* Y[2] = { (__nv_bfloat16*)y_, (__nv_bfloat16*)y_ + NB * MSZ };
    __nv_bfloat16* Z[2] = { (__nv_bfloat16*)z_, (__nv_bfloat16*)z_ + NB * MSZ };
    __nv_bfloat16* T = (__nv_bfloat16*)tt_;

    convert_kernel<<<dim3(KD / 32, ND / 32, NB), dim3(32, 8)>>>(cores);

    // G = Xt * Xt^T (fp32, symmetric: 3 tiles + mirror)
    gemm_t<1024, 0><<<dim3(3, NB), 256, SMEM_GEMM>>>(Xt, Xt, G, Xt, Xt, G,
                                                     (size_t)ND * KD, (size_t)ND * KD);
    powc_kernel<<<NB, 256>>>();
    setup_kernel<<<dim3(8, NB), 256>>>();      // A, T0, Z1 (fused first update)

    // Y1 = A * T0^T
    gemm_t<256, 2><<<dim3(3, NB), 256, SMEM_GEMM>>>(Ab, T, Y[1], Ab, T, Y[1], MSZ, MSZ);

    int cur = 1;
    for (int t = 0; t < NITER; t++) {
        gemm_t<256, 1><<<dim3(3, NB), 256, SMEM_GEMM>>>(Z[cur], Y[cur], T,
                                                        Z[cur], Y[cur], T, MSZ, MSZ);
        gemm_t<256, 2><<<dim3(6, NB), 256, SMEM_GEMM>>>(Y[cur], T, Y[cur ^ 1],
                                                        T, Z[cur], Z[cur ^ 1], MSZ, MSZ);
        cur ^= 1;
    }

    // P = Y*Y^T (fp32) for the first-order trace correction
    gemm_t<256, 0><<<dim3(3, NB), 256, SMEM_GEMM>>>(Y[cur], Y[cur], G,
                                                    Y[cur], Y[cur], G, MSZ, MSZ);
    refine_kernel<<<NB, 256>>>(Y[cur], Z[cur]);
    final_kernel<<<1, 128>>>(out);
}